// round 15
// baseline (speedup 1.0000x reference)
#include <cuda_runtime.h>
#include <cuda_fp16.h>
#include <math.h>
#include <stdint.h>

#define BB 4
#define CC 512
#define TT 1024
#define HH 8
#define KCC 64
#define BHT (BB*HH)

// fp16 staging
__device__ __half g_Qh[BB*HH*TT*KCC];
__device__ __half g_Kh[BB*HH*TT*KCC];
__device__ __half g_Vh[BB*HH*TT*KCC];
__device__ __half g_Oh[BB*HH*TT*KCC];
__device__ __half g_xh[BB*CC*TT];
__device__ __half g_wqh[CC*CC];
__device__ __half g_wkh[CC*CC];
__device__ __half g_wvh[CC*CC];
__device__ __half g_woh[CC*CC];

// ---------------------------------------------------------------------------
// helpers
// ---------------------------------------------------------------------------
__device__ __forceinline__ unsigned h2pack(float x, float y) {
    __half2 t = __floats2half2_rn(x, y);
    return *reinterpret_cast<unsigned*>(&t);
}
__device__ __forceinline__ void mma_f16(float c[4], unsigned a0, unsigned a1,
                                        unsigned a2, unsigned a3,
                                        unsigned b0, unsigned b1) {
    asm volatile(
        "mma.sync.aligned.m16n8k16.row.col.f32.f16.f16.f32 "
        "{%0,%1,%2,%3},{%4,%5,%6,%7},{%8,%9},{%0,%1,%2,%3};"
        : "+f"(c[0]), "+f"(c[1]), "+f"(c[2]), "+f"(c[3])
        : "r"(a0), "r"(a1), "r"(a2), "r"(a3), "r"(b0), "r"(b1));
}
__device__ __forceinline__ void ldmx4(unsigned &r0, unsigned &r1, unsigned &r2, unsigned &r3,
                                      unsigned addr) {
    asm volatile("ldmatrix.sync.aligned.m8n8.x4.shared.b16 {%0,%1,%2,%3},[%4];"
        : "=r"(r0), "=r"(r1), "=r"(r2), "=r"(r3) : "r"(addr));
}
__device__ __forceinline__ void ldmx4t(unsigned &r0, unsigned &r1, unsigned &r2, unsigned &r3,
                                       unsigned addr) {
    asm volatile("ldmatrix.sync.aligned.m8n8.x4.trans.shared.b16 {%0,%1,%2,%3},[%4];"
        : "=r"(r0), "=r"(r1), "=r"(r2), "=r"(r3) : "r"(addr));
}
__device__ __forceinline__ void cpa16(unsigned dst, const void* src) {
    asm volatile("cp.async.cg.shared.global [%0], [%1], 16;" :: "r"(dst), "l"(src));
}
__device__ __forceinline__ void cp_commit() {
    asm volatile("cp.async.commit_group;");
}
template<int N> __device__ __forceinline__ void cp_wait() {
    asm volatile("cp.async.wait_group %0;" :: "n"(N));
}

// ---------------------------------------------------------------------------
// fp32 -> fp16 convert (R14)
// ---------------------------------------------------------------------------
__global__ void cvt_kernel(const float* __restrict__ x,
                           const float* __restrict__ wq, const float* __restrict__ wk,
                           const float* __restrict__ wv, const float* __restrict__ wo,
                           __half* __restrict__ xh,
                           __half* __restrict__ wqh, __half* __restrict__ wkh,
                           __half* __restrict__ wvh, __half* __restrict__ woh)
{
    const int sel = blockIdx.y;
    const float* src; __half* dst; int n;
    if (sel == 0)      { src = x;  dst = xh;  n = BB * CC * TT; }
    else if (sel == 1) { src = wq; dst = wqh; n = CC * CC; }
    else if (sel == 2) { src = wk; dst = wkh; n = CC * CC; }
    else if (sel == 3) { src = wv; dst = wvh; n = CC * CC; }
    else               { src = wo; dst = woh; n = CC * CC; }
    int i = (blockIdx.x * 256 + threadIdx.x) * 8;
    if (i >= n) return;
    float4 a = *(const float4*)(src + i);
    float4 b = *(const float4*)(src + i + 4);
    __half2 h0 = __floats2half2_rn(a.x, a.y);
    __half2 h1 = __floats2half2_rn(a.z, a.w);
    __half2 h2 = __floats2half2_rn(b.x, b.y);
    __half2 h3 = __floats2half2_rn(b.z, b.w);
    *(uint4*)(dst + i) = make_uint4(*(unsigned*)&h0, *(unsigned*)&h1,
                                    *(unsigned*)&h2, *(unsigned*)&h3);
}

// ---------------------------------------------------------------------------
// Fused QKV projection: 64(o) x 128(t) tile, warp 32x32, cp.async pipeline.
// grid (T/128=8, C/64=8, B*3=12) = 768 CTAs, 256 thr.
// ---------------------------------------------------------------------------
__global__ __launch_bounds__(256, 2)
void proj3_kernel(const __half* __restrict__ wq, const float* __restrict__ bq,
                  const __half* __restrict__ wk, const float* __restrict__ bk,
                  const __half* __restrict__ wv, const float* __restrict__ bv,
                  const __half* __restrict__ x,
                  __half* __restrict__ pQ, __half* __restrict__ pK, __half* __restrict__ pV)
{
    const int z   = blockIdx.z;
    const int b   = z & 3;
    const int sel = z >> 2;
    const __half* w   = (sel == 0) ? wq : (sel == 1) ? wk : wv;
    const float* bias = (sel == 0) ? bq : (sel == 1) ? bk : bv;
    __half*      dst  = (sel == 0) ? pQ : (sel == 1) ? pK : pV;

    const int o0 = blockIdx.y * 64;
    const int t0 = blockIdx.x * 128;
    __shared__ __half As[2][64 * 24];    // 3072 B per buf
    __shared__ __half Xs[2][16 * 136];   // 4352 B per buf
    const int tid  = threadIdx.x;
    const int warp = tid >> 5, lane = tid & 31;
    const int m0 = (warp & 1) * 32;
    const int n0 = (warp >> 1) * 32;
    const int lq = lane >> 2, lr = lane & 3;
    const __half* xb = x + (size_t)b * CC * TT;

    const unsigned AsB = (unsigned)__cvta_generic_to_shared(&As[0][0]);
    const unsigned XsB = (unsigned)__cvta_generic_to_shared(&Xs[0][0]);

    // cp.async coords: W = 128 chunks (tid<128), X = 256 chunks
    const int wo_ = tid >> 1, wkk = (tid & 1) * 8;
    const int xk_ = tid >> 4, xt8 = (tid & 15) * 8;
    const unsigned wdst = (wo_ * 24 + wkk) * 2;
    const unsigned xdst = (xk_ * 136 + xt8) * 2;
    const __half* wsrc = w + (size_t)(o0 + wo_) * CC + wkk;
    const __half* xsrc = xb + (size_t)xk_ * TT + t0 + xt8;

    if (tid < 128) cpa16(AsB + wdst, wsrc);
    cpa16(XsB + xdst, xsrc);
    cp_commit();

    const unsigned a_part = ((lane & 15) * 24 + (lane >> 4) * 8) * 2;
    const int mm = lane >> 3, r8 = lane & 7;
    const unsigned b_part = ((((mm & 1) * 8 + r8) * 136) + (mm >> 1) * 8) * 2;

    float acc[2][4][4] = {};

    for (int k0 = 0; k0 < CC; k0 += 16) {
        const int cur = (k0 >> 4) & 1;
        const bool more = (k0 + 16) < CC;
        if (more) {
            const int nxt = cur ^ 1;
            if (tid < 128) cpa16(AsB + nxt * 3072 + wdst, wsrc + k0 + 16);
            cpa16(XsB + nxt * 4352 + xdst, xsrc + (size_t)(k0 + 16) * TT);
            cp_commit();
            cp_wait<1>();
        } else {
            cp_wait<0>();
        }
        __syncthreads();

        unsigned a0[4], a1[4];
        ldmx4(a0[0], a0[1], a0[2], a0[3], AsB + cur * 3072 + m0 * 48 + a_part);
        ldmx4(a1[0], a1[1], a1[2], a1[3], AsB + cur * 3072 + (m0 + 16) * 48 + a_part);
        #pragma unroll
        for (int nt = 0; nt < 2; nt++) {
            unsigned h0, h1, h2, h3;
            ldmx4t(h0, h1, h2, h3, XsB + cur * 4352 + (n0 + nt * 16) * 2 + b_part);
            mma_f16(acc[0][2*nt],   a0[0], a0[1], a0[2], a0[3], h0, h1);
            mma_f16(acc[0][2*nt+1], a0[0], a0[1], a0[2], a0[3], h2, h3);
            mma_f16(acc[1][2*nt],   a1[0], a1[1], a1[2], a1[3], h0, h1);
            mma_f16(acc[1][2*nt+1], a1[0], a1[1], a1[2], a1[3], h2, h3);
        }
        __syncthreads();
    }

    #pragma unroll
    for (int mi = 0; mi < 2; mi++) {
        #pragma unroll
        for (int half = 0; half < 2; half++) {
            int o = o0 + m0 + mi * 16 + half * 8 + lq;
            float bvv = bias[o];
            int h = o >> 6, kc = o & 63;
            __half* drow = dst + ((size_t)(b * HH + h) * TT) * KCC + kc;
            #pragma unroll
            for (int nj = 0; nj < 4; nj++) {
                int t = t0 + n0 + nj * 8 + 2 * lr;
                drow[(size_t)t * KCC]       = __float2half_rn(acc[mi][nj][half * 2 + 0]);
                drow[(size_t)(t + 1) * KCC] = __float2half_rn(acc[mi][nj][half * 2 + 1]);
                drow[(size_t)t * KCC]       = __float2half_rn(acc[mi][nj][half * 2 + 0] + bvv);
                drow[(size_t)(t + 1) * KCC] = __float2half_rn(acc[mi][nj][half * 2 + 1] + bvv);
            }
        }
    }
}

// ---------------------------------------------------------------------------
// MMA banded flash attention (unchanged from R13/R14).
// ---------------------------------------------------------------------------
#define ATTN_SMEM 69120

__global__ __launch_bounds__(256, 2)
void attn_mma_kernel(const __half* __restrict__ Q, const __half* __restrict__ K,
                     const __half* __restrict__ V, const float* __restrict__ embk,
                     const float* __restrict__ embv, __half* __restrict__ Out)
{
    extern __shared__ char smem[];
    __half* Qraw = (__half*)(smem);
    float* pe    = (float*)(smem + 55296);
    float* qe    = (float*)(smem + 59904);
    float* ek    = (float*)(smem + 64512);
    float* ev    = (float*)(smem + 66816);

    const int bh = blockIdx.y;
    const int t0 = blockIdx.x * 128;
    const int tid = threadIdx.x;
    const int w = tid >> 5, lane = tid & 31;
    const int lq = lane >> 2, lr = lane & 3;
    const int R0 = w * 16 + lq;

    const unsigned SB = (unsigned)__cvta_generic_to_shared(smem);
    const unsigned QrawB = SB;
    const unsigned KbB[2] = {SB + 18432, SB + 27648};
    const unsigned VbB[2] = {SB + 36864, SB + 46080};

    const __half* Qg  = Q + ((size_t)bh * TT + t0) * KCC;
    const __half* Kbh = K + (size_t)bh * TT * KCC;
    const __half* Vbh = V + (size_t)bh * TT * KCC;

    #pragma unroll
    for (int i = 0; i < 4; i++) {
        int ii = tid + i * 256;
        int r = ii >> 3, c8 = (ii & 7) * 8;
        cpa16(QrawB + (r * 72 + c8) * 2, Qg + r * 64 + c8);
    }
    cp_commit();
    #pragma unroll
    for (int i = 0; i < 2; i++) {
        int ii = tid + i * 256;
        int s = ii >> 3, c8 = (ii & 7) * 8;
        cpa16(KbB[0] + (s * 72 + c8) * 2, Kbh + s * 64 + c8);
        cpa16(VbB[0] + (s * 72 + c8) * 2, Vbh + s * 64 + c8);
    }
    cp_commit();

    for (int lin = tid; lin < 576; lin += 256) { ek[lin] = embk[lin]; ev[lin] = embv[lin]; }
    for (int lin = tid; lin < 1152; lin += 256) pe[lin] = 0.f;

    cp_wait<1>();
    __syncthreads();

    for (int idx = tid; idx < 1152; idx += 256) {
        int r = idx / 9, d = idx - r * 9;
        const __half2* q2 = (const __half2*)(Qraw + r * 72);
        const float* ekd = ek + d * 64;
        float s = 0.f;
        #pragma unroll 8
        for (int c = 0; c < 32; c++) {
            float2 f = __half22float2(q2[c]);
            s += f.x * ekd[2 * c] + f.y * ekd[2 * c + 1];
        }
        qe[idx] = s;
    }

    const unsigned q_part = ((lane & 15) * 72 + (lane >> 4) * 8) * 2;
    unsigned qf[4][4];
    #pragma unroll
    for (int ks = 0; ks < 4; ks++)
        ldmx4(qf[ks][0], qf[ks][1], qf[ks][2], qf[ks][3],
              QrawB + (w * 16 * 72) * 2 + ks * 32 + q_part);

    const int mm = lane >> 3, r8 = lane & 7;
    const unsigned k_part = ((((mm >> 1) * 8 + r8) * 72) + (mm & 1) * 8) * 2;
    const unsigned v_part = ((((mm & 1) * 8 + r8) * 72) + (mm >> 1) * 8) * 2;

    float S[8][4];
    float O[8][4] = {};
    float mr[2] = {-1e30f, -1e30f};
    float lr2[2] = {0.f, 0.f};
    const int jlo = (t0 - 4) < 0 ? 0 : (t0 - 4) >> 6;
    const int jhi = ((t0 + 131) >> 6) > 15 ? 15 : (t0 + 131) >> 6;

    for (int j = 0; j < 16; j++) {
        const int s0 = j * 64;

        if (j < 15) {
            const int nb = (j + 1) & 1;
            #pragma unroll
            for (int i = 0; i < 2; i++) {
                int ii = tid + i * 256;
                int s = ii >> 3, c8 = (ii & 7) * 8;
                cpa16(KbB[nb] + (s * 72 + c8) * 2, Kbh + (size_t)(s0 + 64 + s) * 64 + c8);
                cpa16(VbB[nb] + (s * 72 + c8) * 2, Vbh + (size_t)(s0 + 64 + s) * 64 + c8);
            }
            cp_commit();
            cp_wait<1>();
        } else {
            cp_wait<0>();
        }
        __syncthreads();

        const unsigned Kj = KbB[j & 1];
        const unsigned Vj = VbB[j & 1];

        #pragma unroll
        for (int nt = 0; nt < 8; nt++)
            #pragma unroll
            for (int sl = 0; sl < 4; sl++) S[nt][sl] = 0.f;

        #pragma unroll
        for (int ks = 0; ks < 4; ks++) {
            #pragma unroll
            for (int ntp = 0; ntp < 4; ntp++) {
                unsigned h0, h1, h2, h3;
                ldmx4(h0, h1, h2, h3, Kj + ntp * 2304 + ks * 32 + k_part);
                mma_f16(S[2*ntp],   qf[ks][0], qf[ks][1], qf[ks][2], qf[ks][3], h0, h1);
                mma_f16(S[2*ntp+1], qf[ks][0], qf[ks][1], qf[ks][2], qf[ks][3], h2, h3);
            }
        }

        const bool band = (j >= jlo) && (j <= jhi);
        if (band) {
            #pragma unroll
            for (int nt = 0; nt < 8; nt++)
                #pragma unroll
                for (int sl = 0; sl < 4; sl++) {
                    int rl = R0 + ((sl >> 1) << 3);
                    int d = (s0 + nt * 8 + 2 * lr + (sl & 1)) - (t0 + rl) + 4;
                    if (d >= 0 && d <= 8) S[nt][sl] += qe[rl * 9 + d];
                }
        }
        #pragma unroll
        for (int nt = 0; nt < 8; nt++)
            #pragma unroll
            for (int sl = 0; sl < 4; sl++) S[nt][sl] *= 0.125f;

        float alpha[2];
        #pragma unroll
        for (int h = 0; h < 2; h++) {
            float mx = -1e30f;
            #pragma unroll
            for (int nt = 0; nt < 8; nt++)
                mx = fmaxf(mx, fmaxf(S[nt][2*h], S[nt][2*h+1]));
            mx = fmaxf(mx, __shfl_xor_sync(0xffffffffu, mx, 1));
            mx = fmaxf(mx, __shfl_xor_sync(0xffffffffu, mx, 2));
            float mn = fmaxf(mr[h], mx);
            alpha[h] = __expf(mr[h] - mn);
            float rs = 0.f;
            #pragma unroll
            for (int nt = 0; nt < 8; nt++) {
                float p0 = __expf(S[nt][2*h]   - mn);
                float p1 = __expf(S[nt][2*h+1] - mn);
                S[nt][2*h] = p0; S[nt][2*h+1] = p1;
                rs += p0 + p1;
            }
            rs += __shfl_xor_sync(0xffffffffu, rs, 1);
            rs += __shfl_xor_sync(0xffffffffu, rs, 2);
            lr2[h] = lr2[h] * alpha[h] + rs;
            mr[h] = mn;
            #pragma unroll
            for (int nt = 0; nt < 8; nt++) { O[nt][2*h] *= alpha[h]; O[nt][2*h+1] *= alpha[h]; }
        }

        if (lr == 0) {
            #pragma unroll
            for (int h = 0; h < 2; h++)
                if (alpha[h] != 1.0f) {
                    #pragma unroll
                    for (int d = 0; d < 9; d++) pe[(R0 + 8*h) * 9 + d] *= alpha[h];
                }
        }
        __syncwarp();
        if (band) {
            #pragma unroll
            for (int nt = 0; nt < 8; nt++)
                #pragma unroll
                for (int sl = 0; sl < 4; sl++) {
                    int rl = R0 + ((sl >> 1) << 3);
                    int d = (s0 + nt * 8 + 2 * lr + (sl & 1)) - (t0 + rl) + 4;
                    if (d >= 0 && d <= 8) pe[rl * 9 + d] += S[nt][sl];
                }
        }
        __syncwarp();

        #pragma unroll
        for (int kp = 0; kp < 4; kp++) {
            unsigned p0 = h2pack(S[2*kp][0],   S[2*kp][1]);
            unsigned p1 = h2pack(S[2*kp][2],   S[2*kp][3]);
            unsigned p2 = h2pack(S[2*kp+1][0], S[2*kp+1][1]);
            unsigned p3 = h2pack(S[2*kp+1][2], S[2*kp+1][3]);
            #pragma unroll
            for (int ntp = 0; ntp < 4; ntp++) {
                unsigned h0, h1, h2, h3;
                ldmx4t(h0, h1, h2, h3, Vj + kp * 2304 + ntp * 32 + v_part);
                mma_f16(O[2*ntp],   p0, p1, p2, p3, h0, h1);
                mma_f16(O[2*ntp+1], p0, p1, p2, p3, h2, h3);
            }
        }
        __syncthreads();
    }

    float pev0[9], pev1[9];
    #pragma unroll
    for (int d = 0; d < 9; d++) { pev0[d] = pe[R0 * 9 + d]; pev1[d] = pe[(R0 + 8) * 9 + d]; }
    const float il0 = 1.f / lr2[0], il1 = 1.f / lr2[1];
    __half* Og = Out + ((size_t)bh * TT + t0) * KCC;
    #pragma unroll
    for (int nt = 0; nt < 8; nt++) {
        int c = nt * 8 + 2 * lr;
        float e0 = 0.f, e1 = 0.f, f0 = 0.f, f1 = 0.f;
        #pragma unroll
        for (int d = 0; d < 9; d++) {
            float v0 = ev[d * 64 + c], v1 = ev[d * 64 + c + 1];
            e0 += pev0[d] * v0; e1 += pev0[d] * v1;
            f0 += pev1[d] * v0; f1 += pev1[d] * v1;
        }
        *(__half2*)(Og + (size_t)R0 * 64 + c) =
            __floats2half2_rn((O[nt][0] + e0) * il0, (O[nt][1] + e1) * il0);
        *(__half2*)(Og + (size_t)(R0 + 8) * 64 + c) =
            __floats2half2_rn((O[nt][2] + f0) * il1, (O[nt][3] + f1) * il1);
    }
}

// ---------------------------------------------------------------------------
// Output projection: 64(o) x 128(t) tile, warp 32x32, cp.async pipeline.
// grid (8, 8, 4) = 256 CTAs.
// ---------------------------------------------------------------------------
__global__ __launch_bounds__(256, 2)
void oproj_kernel(const __half* __restrict__ w, const float* __restrict__ bias,
                  const __half* __restrict__ A, float* __restrict__ out)
{
    const int b  = blockIdx.z;
    const int o0 = blockIdx.y * 64;
    const int t0 = blockIdx.x * 128;
    __shared__ __half As[2][64 * 24];    // 3072 B per buf
    __shared__ __half Xs[2][128 * 24];   // 6144 B per buf
    const int tid  = threadIdx.x;
    const int warp = tid >> 5, lane = tid & 31;
    const int m0 = (warp & 1) * 32;
    const int n0 = (warp >> 1) * 32;
    const int lq = lane >> 2, lr = lane & 3;

    const unsigned AsB = (unsigned)__cvta_generic_to_shared(&As[0][0]);
    const unsigned XsB = (unsigned)__cvta_generic_to_shared(&Xs[0][0]);

    const int wo_ = tid >> 1, wkk = (tid & 1) * 8;
    const int xt_ = tid >> 1, xkk = (tid & 1) * 8;
    const unsigned wdst = (wo_ * 24 + wkk) * 2;
    const unsigned xdst = (xt_ * 24 + xkk) * 2;
    const __half* wsrc = w + (size_t)(o0 + wo_) * CC + wkk;
    const __half* Ab = A + (size_t)(b * HH) * TT * KCC;

    if (tid < 128) cpa16(AsB + wdst, wsrc);
    cpa16(XsB + xdst, Ab + (size_t)(t0 + xt_) * KCC + xkk);
    cp_commit();

    const unsigned a_part = ((lane & 15) * 24 + (lane >> 4) * 8) * 2;

    float acc[2][4][4] = {};

    for (int k0 = 0; k0 < CC; k0 += 16) {
        const int cur = (k0 >> 4) & 1;
        const bool more = (k0 + 16) < CC;
        if (more) {
            const int kn = k0 + 16;
            const int h = kn >> 6, kc0 = kn & 63;
            const int nxt = cur ^ 1;
            if (tid < 128) cpa16(AsB + nxt * 3072 + wdst, wsrc + kn);
            cpa16(XsB + nxt * 6144 + xdst,
                  Ab + ((size_t)h * TT + t0 + xt_) * KCC + kc0 + xkk);
            cp_commit();
            cp_wait<1>();
        } else {
            cp_wait<0>();
        }
        __syncthreads();

        unsigned a0[4], a1[4];
        ldmx4(a0[0], a0[1], a0[2], a0[3], AsB + cur * 3072 + m0 * 48 + a_part);
        ldmx4(a1[0], a1[1], a1[2], a1[3], AsB + cur * 3072 + (m0 + 16) * 48 + a_part);
        #pragma unroll
        for (int nt = 0; nt < 2; nt++) {
            unsigned h0, h1, h2, h3;
            ldmx4(h0, h1, h2, h3, XsB + cur * 6144 + (n0 + nt * 16) * 48 + a_part);
            mma_f16(acc[0][2*nt],   a0[0], a0[1], a0[2], a0[3], h0, h2);
            mma_f16(acc[0][2*nt+1], a0[0], a0[1], a0[2], a0[3], h1, h3);
            mma_f16(acc[1][2*nt],   a1[0], a1[1], a1[2], a1[3], h0, h2);
            mma_f16(acc[1][2*nt+1], a1[0], a1[1], a1[2], a1[3], h1, h3);
        }
        __syncthreads();
    }

    #pragma unroll
    for (int mi = 0; mi < 2; mi++) {
        #pragma unroll
        for (int half = 0; half < 2; half++) {
            int o = o0 + m0 + mi * 16 + half * 8 + lq;
            float bvv = bias[o];
            float* orow = out + ((size_t)b * CC + o) * TT;
            #pragma unroll
            for (int nj = 0; nj < 4; nj++) {
                int t = t0 + n0 + nj * 8 + 2 * lr;
                *(float2*)(orow + t) = make_float2(acc[mi][nj][half * 2 + 0] + bvv,
                                                   acc[mi][nj][half * 2 + 1] + bvv);
            }
        }
    }
}

// ---------------------------------------------------------------------------
extern "C" void kernel_launch(void* const* d_in, const int* in_sizes, int n_in,
                              void* d_out, int out_size)
{
    const float* x   = (const float*)d_in[0];
    const float* wq  = (const float*)d_in[1];
    const float* bq  = (const float*)d_in[2];
    const float* wk  = (const float*)d_in[3];
    const float* bk  = (const float*)d_in[4];
    const float* wv  = (const float*)d_in[5];
    const float* bv  = (const float*)d_in[6];
    const float* wo  = (const float*)d_in[7];
    const float* bo  = (const float*)d_in[8];
    const float* ek  = (const float*)d_in[9];
    const float* ev  = (const float*)d_in[10];
    float* out = (float*)d_out;

    __half *pQ, *pK, *pV, *pO, *pxh, *pwq, *pwk, *pwv, *pwo;
    cudaGetSymbolAddress((void**)&pQ,  g_Qh);
    cudaGetSymbolAddress((void**)&pK,  g_Kh);
    cudaGetSymbolAddress((void**)&pV,  g_Vh);
    cudaGetSymbolAddress((void**)&pO,  g_Oh);
    cudaGetSymbolAddress((void**)&pxh, g_xh);
    cudaGetSymbolAddress((void**)&pwq, g_wqh);
    cudaGetSymbolAddress((void**)&pwk, g_wkh);
    cudaGetSymbolAddress((void**)&pwv, g_wvh);
    cudaGetSymbolAddress((void**)&pwo, g_woh);

    static int configured = 0;
    if (!configured) {
        cudaFuncSetAttribute((const void*)attn_mma_kernel,
                             cudaFuncAttributeMaxDynamicSharedMemorySize, ATTN_SMEM);
        configured = 1;
    }

    cvt_kernel<<<dim3((BB * CC * TT) / 2048, 5), 256>>>(x, wq, wk, wv, wo,
                                                        pxh, pwq, pwk, pwv, pwo);
    proj3_kernel<<<dim3(TT / 128, CC / 64, BB * 3), 256>>>(pwq, bq, pwk, bk, pwv, bv,
                                                           pxh, pQ, pK, pV);
    attn_mma_kernel<<<dim3(TT / 128, BHT), 256, ATTN_SMEM>>>(pQ, pK, pV, ek, ev, pO);
    oproj_kernel<<<dim3(TT / 128, CC / 64, BB), 256>>>(pwo, bo, pO, out);
}

// round 16
// speedup vs baseline: 1.1178x; 1.1178x over previous
#include <cuda_runtime.h>
#include <cuda_fp16.h>
#include <math.h>
#include <stdint.h>

#define BB 4
#define CC 512
#define TT 1024
#define HH 8
#define KCC 64
#define BHT (BB*HH)

// fp16 staging
__device__ __half g_Qh[BB*HH*TT*KCC];
__device__ __half g_Kh[BB*HH*TT*KCC];
__device__ __half g_Vh[BB*HH*TT*KCC];
__device__ __half g_Oh[BB*HH*TT*KCC];
__device__ __half g_xh[BB*CC*TT];
__device__ __half g_wqh[CC*CC];
__device__ __half g_wkh[CC*CC];
__device__ __half g_wvh[CC*CC];
__device__ __half g_woh[CC*CC];

// ---------------------------------------------------------------------------
// helpers
// ---------------------------------------------------------------------------
__device__ __forceinline__ unsigned h2pack(float x, float y) {
    __half2 t = __floats2half2_rn(x, y);
    return *reinterpret_cast<unsigned*>(&t);
}
__device__ __forceinline__ void mma_f16(float c[4], unsigned a0, unsigned a1,
                                        unsigned a2, unsigned a3,
                                        unsigned b0, unsigned b1) {
    asm volatile(
        "mma.sync.aligned.m16n8k16.row.col.f32.f16.f16.f32 "
        "{%0,%1,%2,%3},{%4,%5,%6,%7},{%8,%9},{%0,%1,%2,%3};"
        : "+f"(c[0]), "+f"(c[1]), "+f"(c[2]), "+f"(c[3])
        : "r"(a0), "r"(a1), "r"(a2), "r"(a3), "r"(b0), "r"(b1));
}
__device__ __forceinline__ void ldmx4(unsigned &r0, unsigned &r1, unsigned &r2, unsigned &r3,
                                      unsigned addr) {
    asm volatile("ldmatrix.sync.aligned.m8n8.x4.shared.b16 {%0,%1,%2,%3},[%4];"
        : "=r"(r0), "=r"(r1), "=r"(r2), "=r"(r3) : "r"(addr));
}
__device__ __forceinline__ void ldmx4t(unsigned &r0, unsigned &r1, unsigned &r2, unsigned &r3,
                                       unsigned addr) {
    asm volatile("ldmatrix.sync.aligned.m8n8.x4.trans.shared.b16 {%0,%1,%2,%3},[%4];"
        : "=r"(r0), "=r"(r1), "=r"(r2), "=r"(r3) : "r"(addr));
}
__device__ __forceinline__ void cpa16(unsigned dst, const void* src) {
    asm volatile("cp.async.cg.shared.global [%0], [%1], 16;" :: "r"(dst), "l"(src));
}
__device__ __forceinline__ void cp_commit() {
    asm volatile("cp.async.commit_group;");
}
template<int N> __device__ __forceinline__ void cp_wait() {
    asm volatile("cp.async.wait_group %0;" :: "n"(N));
}

// ---------------------------------------------------------------------------
// fp32 -> fp16 convert (R14)
// ---------------------------------------------------------------------------
__global__ void cvt_kernel(const float* __restrict__ x,
                           const float* __restrict__ wq, const float* __restrict__ wk,
                           const float* __restrict__ wv, const float* __restrict__ wo,
                           __half* __restrict__ xh,
                           __half* __restrict__ wqh, __half* __restrict__ wkh,
                           __half* __restrict__ wvh, __half* __restrict__ woh)
{
    const int sel = blockIdx.y;
    const float* src; __half* dst; int n;
    if (sel == 0)      { src = x;  dst = xh;  n = BB * CC * TT; }
    else if (sel == 1) { src = wq; dst = wqh; n = CC * CC; }
    else if (sel == 2) { src = wk; dst = wkh; n = CC * CC; }
    else if (sel == 3) { src = wv; dst = wvh; n = CC * CC; }
    else               { src = wo; dst = woh; n = CC * CC; }
    int i = (blockIdx.x * 256 + threadIdx.x) * 8;
    if (i >= n) return;
    float4 a = *(const float4*)(src + i);
    float4 b = *(const float4*)(src + i + 4);
    __half2 h0 = __floats2half2_rn(a.x, a.y);
    __half2 h1 = __floats2half2_rn(a.z, a.w);
    __half2 h2 = __floats2half2_rn(b.x, b.y);
    __half2 h3 = __floats2half2_rn(b.z, b.w);
    *(uint4*)(dst + i) = make_uint4(*(unsigned*)&h0, *(unsigned*)&h1,
                                    *(unsigned*)&h2, *(unsigned*)&h3);
}

// ---------------------------------------------------------------------------
// Fused QKV projection: 128(o) x 128(t), BK=32 double-buffered cp.async.
// As[o][k] pitch 40 (10240 B/buf); Xs[k][t] pitch 136 (8704 B/buf).
// grid (T/128, C/128, B*3) = 384 CTAs, 256 thr.
// ---------------------------------------------------------------------------
__global__ __launch_bounds__(256, 2)
void proj3_kernel(const __half* __restrict__ wq, const float* __restrict__ bq,
                  const __half* __restrict__ wk, const float* __restrict__ bk,
                  const __half* __restrict__ wv, const float* __restrict__ bv,
                  const __half* __restrict__ x,
                  __half* __restrict__ pQ, __half* __restrict__ pK, __half* __restrict__ pV)
{
    const int z   = blockIdx.z;
    const int b   = z & 3;
    const int sel = z >> 2;
    const __half* w   = (sel == 0) ? wq : (sel == 1) ? wk : wv;
    const float* bias = (sel == 0) ? bq : (sel == 1) ? bk : bv;
    __half*      dst  = (sel == 0) ? pQ : (sel == 1) ? pK : pV;

    const int o0 = blockIdx.y * 128;
    const int t0 = blockIdx.x * 128;
    __shared__ __half As[2][128 * 40];   // [buf][o][k0..31 +pad8]
    __shared__ __half Xs[2][32 * 136];   // [buf][k][t0..127 +pad8]
    const int tid  = threadIdx.x;
    const int warp = tid >> 5, lane = tid & 31;
    const int m0 = (warp >> 1) * 32;
    const int n0 = (warp & 1) * 64;
    const int lq = lane >> 2, lr = lane & 3;
    const __half* xb = x + (size_t)b * CC * TT;

    const unsigned AsB = (unsigned)__cvta_generic_to_shared(&As[0][0]);
    const unsigned XsB = (unsigned)__cvta_generic_to_shared(&Xs[0][0]);

    // W: 512 chunks (row o, 4 k-chunks); X: 512 chunks (row k, 16 t-chunks)
    const int wr0 = tid >> 2,            wk0 = (tid & 3) * 8;
    const int wr1 = (tid + 256) >> 2,    wk1 = (tid & 3) * 8;   // rows 64..127
    const int xk0 = tid >> 4,            xt0 = (tid & 15) * 8;
    const int xk1 = (tid + 256) >> 4,    xt1 = (tid & 15) * 8;  // k rows 16..31
    const unsigned wdst0 = (wr0 * 40 + wk0) * 2, wdst1 = (wr1 * 40 + wk1) * 2;
    const unsigned xdst0 = (xk0 * 136 + xt0) * 2, xdst1 = (xk1 * 136 + xt1) * 2;
    const __half* wsrc0 = w + (size_t)(o0 + wr0) * CC + wk0;
    const __half* wsrc1 = w + (size_t)(o0 + wr1) * CC + wk1;
    const __half* xsrc0 = xb + (size_t)xk0 * TT + t0 + xt0;
    const __half* xsrc1 = xb + (size_t)xk1 * TT + t0 + xt1;

    // prologue: stage 0
    cpa16(AsB + wdst0, wsrc0);
    cpa16(AsB + wdst1, wsrc1);
    cpa16(XsB + xdst0, xsrc0);
    cpa16(XsB + xdst1, xsrc1);
    cp_commit();

    const unsigned a_part = ((lane & 15) * 40 + (lane >> 4) * 8) * 2;
    const int mm = lane >> 3, r8 = lane & 7;
    const unsigned b_part = ((((mm & 1) * 8 + r8) * 136) + (mm >> 1) * 8) * 2;

    float acc[2][8][4] = {};

    for (int k0 = 0; k0 < CC; k0 += 32) {
        const int cur = (k0 >> 5) & 1;
        const bool more = (k0 + 32) < CC;
        if (more) {
            const int nxt = cur ^ 1;
            const int kn = k0 + 32;
            cpa16(AsB + nxt * 10240 + wdst0, wsrc0 + kn);
            cpa16(AsB + nxt * 10240 + wdst1, wsrc1 + kn);
            cpa16(XsB + nxt * 8704 + xdst0, xsrc0 + (size_t)kn * TT);
            cpa16(XsB + nxt * 8704 + xdst1, xsrc1 + (size_t)kn * TT);
            cp_commit();
            cp_wait<1>();
        } else {
            cp_wait<0>();
        }
        __syncthreads();

        #pragma unroll
        for (int ks = 0; ks < 32; ks += 16) {
            unsigned a0[4], a1[4];
            ldmx4(a0[0], a0[1], a0[2], a0[3],
                  AsB + cur * 10240 + m0 * 80 + ks * 2 + a_part);
            ldmx4(a1[0], a1[1], a1[2], a1[3],
                  AsB + cur * 10240 + (m0 + 16) * 80 + ks * 2 + a_part);
            #pragma unroll
            for (int nt = 0; nt < 4; nt++) {
                unsigned h0, h1, h2, h3;
                ldmx4t(h0, h1, h2, h3,
                       XsB + cur * 8704 + ks * 272 + (n0 + nt * 16) * 2 + b_part);
                mma_f16(acc[0][2*nt],   a0[0], a0[1], a0[2], a0[3], h0, h1);
                mma_f16(acc[0][2*nt+1], a0[0], a0[1], a0[2], a0[3], h2, h3);
                mma_f16(acc[1][2*nt],   a1[0], a1[1], a1[2], a1[3], h0, h1);
                mma_f16(acc[1][2*nt+1], a1[0], a1[1], a1[2], a1[3], h2, h3);
            }
        }
        __syncthreads();
    }

    #pragma unroll
    for (int mi = 0; mi < 2; mi++) {
        #pragma unroll
        for (int half = 0; half < 2; half++) {
            int o = o0 + m0 + mi * 16 + half * 8 + lq;
            float bvv = bias[o];
            int h = o >> 6, kc = o & 63;
            __half* drow = dst + ((size_t)(b * HH + h) * TT) * KCC + kc;
            #pragma unroll
            for (int nj = 0; nj < 8; nj++) {
                int t = t0 + n0 + nj * 8 + 2 * lr;
                drow[(size_t)t * KCC]       = __float2half_rn(acc[mi][nj][half * 2 + 0] + bvv);
                drow[(size_t)(t + 1) * KCC] = __float2half_rn(acc[mi][nj][half * 2 + 1] + bvv);
            }
        }
    }
}

// ---------------------------------------------------------------------------
// MMA banded flash attention (unchanged from R13/R14).
// ---------------------------------------------------------------------------
#define ATTN_SMEM 69120

__global__ __launch_bounds__(256, 2)
void attn_mma_kernel(const __half* __restrict__ Q, const __half* __restrict__ K,
                     const __half* __restrict__ V, const float* __restrict__ embk,
                     const float* __restrict__ embv, __half* __restrict__ Out)
{
    extern __shared__ char smem[];
    __half* Qraw = (__half*)(smem);
    float* pe    = (float*)(smem + 55296);
    float* qe    = (float*)(smem + 59904);
    float* ek    = (float*)(smem + 64512);
    float* ev    = (float*)(smem + 66816);

    const int bh = blockIdx.y;
    const int t0 = blockIdx.x * 128;
    const int tid = threadIdx.x;
    const int w = tid >> 5, lane = tid & 31;
    const int lq = lane >> 2, lr = lane & 3;
    const int R0 = w * 16 + lq;

    const unsigned SB = (unsigned)__cvta_generic_to_shared(smem);
    const unsigned QrawB = SB;
    const unsigned KbB[2] = {SB + 18432, SB + 27648};
    const unsigned VbB[2] = {SB + 36864, SB + 46080};

    const __half* Qg  = Q + ((size_t)bh * TT + t0) * KCC;
    const __half* Kbh = K + (size_t)bh * TT * KCC;
    const __half* Vbh = V + (size_t)bh * TT * KCC;

    #pragma unroll
    for (int i = 0; i < 4; i++) {
        int ii = tid + i * 256;
        int r = ii >> 3, c8 = (ii & 7) * 8;
        cpa16(QrawB + (r * 72 + c8) * 2, Qg + r * 64 + c8);
    }
    cp_commit();
    #pragma unroll
    for (int i = 0; i < 2; i++) {
        int ii = tid + i * 256;
        int s = ii >> 3, c8 = (ii & 7) * 8;
        cpa16(KbB[0] + (s * 72 + c8) * 2, Kbh + s * 64 + c8);
        cpa16(VbB[0] + (s * 72 + c8) * 2, Vbh + s * 64 + c8);
    }
    cp_commit();

    for (int lin = tid; lin < 576; lin += 256) { ek[lin] = embk[lin]; ev[lin] = embv[lin]; }
    for (int lin = tid; lin < 1152; lin += 256) pe[lin] = 0.f;

    cp_wait<1>();
    __syncthreads();

    for (int idx = tid; idx < 1152; idx += 256) {
        int r = idx / 9, d = idx - r * 9;
        const __half2* q2 = (const __half2*)(Qraw + r * 72);
        const float* ekd = ek + d * 64;
        float s = 0.f;
        #pragma unroll 8
        for (int c = 0; c < 32; c++) {
            float2 f = __half22float2(q2[c]);
            s += f.x * ekd[2 * c] + f.y * ekd[2 * c + 1];
        }
        qe[idx] = s;
    }

    const unsigned q_part = ((lane & 15) * 72 + (lane >> 4) * 8) * 2;
    unsigned qf[4][4];
    #pragma unroll
    for (int ks = 0; ks < 4; ks++)
        ldmx4(qf[ks][0], qf[ks][1], qf[ks][2], qf[ks][3],
              QrawB + (w * 16 * 72) * 2 + ks * 32 + q_part);

    const int mm = lane >> 3, r8 = lane & 7;
    const unsigned k_part = ((((mm >> 1) * 8 + r8) * 72) + (mm & 1) * 8) * 2;
    const unsigned v_part = ((((mm & 1) * 8 + r8) * 72) + (mm >> 1) * 8) * 2;

    float S[8][4];
    float O[8][4] = {};
    float mr[2] = {-1e30f, -1e30f};
    float lr2[2] = {0.f, 0.f};
    const int jlo = (t0 - 4) < 0 ? 0 : (t0 - 4) >> 6;
    const int jhi = ((t0 + 131) >> 6) > 15 ? 15 : (t0 + 131) >> 6;

    for (int j = 0; j < 16; j++) {
        const int s0 = j * 64;

        if (j < 15) {
            const int nb = (j + 1) & 1;
            #pragma unroll
            for (int i = 0; i < 2; i++) {
                int ii = tid + i * 256;
                int s = ii >> 3, c8 = (ii & 7) * 8;
                cpa16(KbB[nb] + (s * 72 + c8) * 2, Kbh + (size_t)(s0 + 64 + s) * 64 + c8);
                cpa16(VbB[nb] + (s * 72 + c8) * 2, Vbh + (size_t)(s0 + 64 + s) * 64 + c8);
            }
            cp_commit();
            cp_wait<1>();
        } else {
            cp_wait<0>();
        }
        __syncthreads();

        const unsigned Kj = KbB[j & 1];
        const unsigned Vj = VbB[j & 1];

        #pragma unroll
        for (int nt = 0; nt < 8; nt++)
            #pragma unroll
            for (int sl = 0; sl < 4; sl++) S[nt][sl] = 0.f;

        #pragma unroll
        for (int ks = 0; ks < 4; ks++) {
            #pragma unroll
            for (int ntp = 0; ntp < 4; ntp++) {
                unsigned h0, h1, h2, h3;
                ldmx4(h0, h1, h2, h3, Kj + ntp * 2304 + ks * 32 + k_part);
                mma_f16(S[2*ntp],   qf[ks][0], qf[ks][1], qf[ks][2], qf[ks][3], h0, h1);
                mma_f16(S[2*ntp+1], qf[ks][0], qf[ks][1], qf[ks][2], qf[ks][3], h2, h3);
            }
        }

        const bool band = (j >= jlo) && (j <= jhi);
        if (band) {
            #pragma unroll
            for (int nt = 0; nt < 8; nt++)
                #pragma unroll
                for (int sl = 0; sl < 4; sl++) {
                    int rl = R0 + ((sl >> 1) << 3);
                    int d = (s0 + nt * 8 + 2 * lr + (sl & 1)) - (t0 + rl) + 4;
                    if (d >= 0 && d <= 8) S[nt][sl] += qe[rl * 9 + d];
                }
        }
        #pragma unroll
        for (int nt = 0; nt < 8; nt++)
            #pragma unroll
            for (int sl = 0; sl < 4; sl++) S[nt][sl] *= 0.125f;

        float alpha[2];
        #pragma unroll
        for (int h = 0; h < 2; h++) {
            float mx = -1e30f;
            #pragma unroll
            for (int nt = 0; nt < 8; nt++)
                mx = fmaxf(mx, fmaxf(S[nt][2*h], S[nt][2*h+1]));
            mx = fmaxf(mx, __shfl_xor_sync(0xffffffffu, mx, 1));
            mx = fmaxf(mx, __shfl_xor_sync(0xffffffffu, mx, 2));
            float mn = fmaxf(mr[h], mx);
            alpha[h] = __expf(mr[h] - mn);
            float rs = 0.f;
            #pragma unroll
            for (int nt = 0; nt < 8; nt++) {
                float p0 = __expf(S[nt][2*h]   - mn);
                float p1 = __expf(S[nt][2*h+1] - mn);
                S[nt][2*h] = p0; S[nt][2*h+1] = p1;
                rs += p0 + p1;
            }
            rs += __shfl_xor_sync(0xffffffffu, rs, 1);
            rs += __shfl_xor_sync(0xffffffffu, rs, 2);
            lr2[h] = lr2[h] * alpha[h] + rs;
            mr[h] = mn;
            #pragma unroll
            for (int nt = 0; nt < 8; nt++) { O[nt][2*h] *= alpha[h]; O[nt][2*h+1] *= alpha[h]; }
        }

        if (lr == 0) {
            #pragma unroll
            for (int h = 0; h < 2; h++)
                if (alpha[h] != 1.0f) {
                    #pragma unroll
                    for (int d = 0; d < 9; d++) pe[(R0 + 8*h) * 9 + d] *= alpha[h];
                }
        }
        __syncwarp();
        if (band) {
            #pragma unroll
            for (int nt = 0; nt < 8; nt++)
                #pragma unroll
                for (int sl = 0; sl < 4; sl++) {
                    int rl = R0 + ((sl >> 1) << 3);
                    int d = (s0 + nt * 8 + 2 * lr + (sl & 1)) - (t0 + rl) + 4;
                    if (d >= 0 && d <= 8) pe[rl * 9 + d] += S[nt][sl];
                }
        }
        __syncwarp();

        #pragma unroll
        for (int kp = 0; kp < 4; kp++) {
            unsigned p0 = h2pack(S[2*kp][0],   S[2*kp][1]);
            unsigned p1 = h2pack(S[2*kp][2],   S[2*kp][3]);
            unsigned p2 = h2pack(S[2*kp+1][0], S[2*kp+1][1]);
            unsigned p3 = h2pack(S[2*kp+1][2], S[2*kp+1][3]);
            #pragma unroll
            for (int ntp = 0; ntp < 4; ntp++) {
                unsigned h0, h1, h2, h3;
                ldmx4t(h0, h1, h2, h3, Vj + kp * 2304 + ntp * 32 + v_part);
                mma_f16(O[2*ntp],   p0, p1, p2, p3, h0, h1);
                mma_f16(O[2*ntp+1], p0, p1, p2, p3, h2, h3);
            }
        }
        __syncthreads();
    }

    float pev0[9], pev1[9];
    #pragma unroll
    for (int d = 0; d < 9; d++) { pev0[d] = pe[R0 * 9 + d]; pev1[d] = pe[(R0 + 8) * 9 + d]; }
    const float il0 = 1.f / lr2[0], il1 = 1.f / lr2[1];
    __half* Og = Out + ((size_t)bh * TT + t0) * KCC;
    #pragma unroll
    for (int nt = 0; nt < 8; nt++) {
        int c = nt * 8 + 2 * lr;
        float e0 = 0.f, e1 = 0.f, f0 = 0.f, f1 = 0.f;
        #pragma unroll
        for (int d = 0; d < 9; d++) {
            float v0 = ev[d * 64 + c], v1 = ev[d * 64 + c + 1];
            e0 += pev0[d] * v0; e1 += pev0[d] * v1;
            f0 += pev1[d] * v0; f1 += pev1[d] * v1;
        }
        *(__half2*)(Og + (size_t)R0 * 64 + c) =
            __floats2half2_rn((O[nt][0] + e0) * il0, (O[nt][1] + e1) * il0);
        *(__half2*)(Og + (size_t)(R0 + 8) * 64 + c) =
            __floats2half2_rn((O[nt][2] + f0) * il1, (O[nt][3] + f1) * il1);
    }
}

// ---------------------------------------------------------------------------
// Output projection: 128(o) x 128(t), BK=32 double-buffered cp.async.
// As[o][k] pitch 40; Xs[t][k] pitch 40.
// ---------------------------------------------------------------------------
__global__ __launch_bounds__(256, 2)
void oproj_kernel(const __half* __restrict__ w, const float* __restrict__ bias,
                  const __half* __restrict__ A, float* __restrict__ out)
{
    const int b  = blockIdx.z;
    const int o0 = blockIdx.y * 128;
    const int t0 = blockIdx.x * 128;
    __shared__ __half As[2][128 * 40];
    __shared__ __half Xs[2][128 * 40];
    const int tid  = threadIdx.x;
    const int warp = tid >> 5, lane = tid & 31;
    const int m0 = (warp >> 1) * 32;
    const int n0 = (warp & 1) * 64;
    const int lq = lane >> 2, lr = lane & 3;

    const unsigned AsB = (unsigned)__cvta_generic_to_shared(&As[0][0]);
    const unsigned XsB = (unsigned)__cvta_generic_to_shared(&Xs[0][0]);

    const int wr0 = tid >> 2,         wk0 = (tid & 3) * 8;
    const int wr1 = (tid + 256) >> 2;
    const int xt0 = tid >> 2,         xk0 = (tid & 3) * 8;
    const int xt1 = (tid + 256) >> 2;
    const unsigned wdst0 = (wr0 * 40 + wk0) * 2, wdst1 = (wr1 * 40 + wk0) * 2;
    const unsigned xdst0 = (xt0 * 40 + xk0) * 2, xdst1 = (xt1 * 40 + xk0) * 2;
    const __half* wsrc0 = w + (size_t)(o0 + wr0) * CC + wk0;
    const __half* wsrc1 = w + (size_t)(o0 + wr1) * CC + wk0;
    const __half* Ab = A + (size_t)(b * HH) * TT * KCC;

    // prologue k0=0 (h=0, kc0=0)
    cpa16(AsB + wdst0, wsrc0);
    cpa16(AsB + wdst1, wsrc1);
    cpa16(XsB + xdst0, Ab + (size_t)(t0 + xt0) * KCC + xk0);
    cpa16(XsB + xdst1, Ab + (size_t)(t0 + xt1) * KCC + xk0);
    cp_commit();

    const unsigned a_part = ((lane & 15) * 40 + (lane >> 4) * 8) * 2;

    float acc[2][8][4] = {};

    for (int k0 = 0; k0 < CC; k0 += 32) {
        const int cur = (k0 >> 5) & 1;
        const bool more = (k0 + 32) < CC;
        if (more) {
            const int kn = k0 + 32;
            const int h = kn >> 6, kc0 = kn & 63;
            const int nxt = cur ^ 1;
            cpa16(AsB + nxt * 10240 + wdst0, wsrc0 + kn);
            cpa16(AsB + nxt * 10240 + wdst1, wsrc1 + kn);
            cpa16(XsB + nxt * 10240 + xdst0,
                  Ab + ((size_t)h * TT + t0 + xt0) * KCC + kc0 + xk0);
            cpa16(XsB + nxt * 10240 + xdst1,
                  Ab + ((size_t)h * TT + t0 + xt1) * KCC + kc0 + xk0);
            cp_commit();
            cp_wait<1>();
        } else {
            cp_wait<0>();
        }
        __syncthreads();

        #pragma unroll
        for (int ks = 0; ks < 32; ks += 16) {
            unsigned a0[4], a1[4];
            ldmx4(a0[0], a0[1], a0[2], a0[3],
                  AsB + cur * 10240 + m0 * 80 + ks * 2 + a_part);
            ldmx4(a1[0], a1[1], a1[2], a1[3],
                  AsB + cur * 10240 + (m0 + 16) * 80 + ks * 2 + a_part);
            #pragma unroll
            for (int nt = 0; nt < 4; nt++) {
                unsigned h0, h1, h2, h3;
                ldmx4(h0, h1, h2, h3,
                      XsB + cur * 10240 + (n0 + nt * 16) * 80 + ks * 2 + a_part);
                mma_f16(acc[0][2*nt],   a0[0], a0[1], a0[2], a0[3], h0, h2);
                mma_f16(acc[0][2*nt+1], a0[0], a0[1], a0[2], a0[3], h1, h3);
                mma_f16(acc[1][2*nt],   a1[0], a1[1], a1[2], a1[3], h0, h2);
                mma_f16(acc[1][2*nt+1], a1[0], a1[1], a1[2], a1[3], h1, h3);
            }
        }
        __syncthreads();
    }

    #pragma unroll
    for (int mi = 0; mi < 2; mi++) {
        #pragma unroll
        for (int half = 0; half < 2; half++) {
            int o = o0 + m0 + mi * 16 + half * 8 + lq;
            float bvv = bias[o];
            float* orow = out + ((size_t)b * CC + o) * TT;
            #pragma unroll
            for (int nj = 0; nj < 8; nj++) {
                int t = t0 + n0 + nj * 8 + 2 * lr;
                *(float2*)(orow + t) = make_float2(acc[mi][nj][half * 2 + 0] + bvv,
                                                   acc[mi][nj][half * 2 + 1] + bvv);
            }
        }
    }
}

// ---------------------------------------------------------------------------
extern "C" void kernel_launch(void* const* d_in, const int* in_sizes, int n_in,
                              void* d_out, int out_size)
{
    const float* x   = (const float*)d_in[0];
    const float* wq  = (const float*)d_in[1];
    const float* bq  = (const float*)d_in[2];
    const float* wk  = (const float*)d_in[3];
    const float* bk  = (const float*)d_in[4];
    const float* wv  = (const float*)d_in[5];
    const float* bv  = (const float*)d_in[6];
    const float* wo  = (const float*)d_in[7];
    const float* bo  = (const float*)d_in[8];
    const float* ek  = (const float*)d_in[9];
    const float* ev  = (const float*)d_in[10];
    float* out = (float*)d_out;

    __half *pQ, *pK, *pV, *pO, *pxh, *pwq, *pwk, *pwv, *pwo;
    cudaGetSymbolAddress((void**)&pQ,  g_Qh);
    cudaGetSymbolAddress((void**)&pK,  g_Kh);
    cudaGetSymbolAddress((void**)&pV,  g_Vh);
    cudaGetSymbolAddress((void**)&pO,  g_Oh);
    cudaGetSymbolAddress((void**)&pxh, g_xh);
    cudaGetSymbolAddress((void**)&pwq, g_wqh);
    cudaGetSymbolAddress((void**)&pwk, g_wkh);
    cudaGetSymbolAddress((void**)&pwv, g_wvh);
    cudaGetSymbolAddress((void**)&pwo, g_woh);

    static int configured = 0;
    if (!configured) {
        cudaFuncSetAttribute((const void*)attn_mma_kernel,
                             cudaFuncAttributeMaxDynamicSharedMemorySize, ATTN_SMEM);
        configured = 1;
    }

    cvt_kernel<<<dim3((BB * CC * TT) / 2048, 5), 256>>>(x, wq, wk, wv, wo,
                                                        pxh, pwq, pwk, pwv, pwo);
    proj3_kernel<<<dim3(TT / 128, CC / 128, BB * 3), 256>>>(pwq, bq, pwk, bk, pwv, bv,
                                                            pxh, pQ, pK, pV);
    attn_mma_kernel<<<dim3(TT / 128, BHT), 256, ATTN_SMEM>>>(pQ, pK, pV, ek, ev, pO);
    oproj_kernel<<<dim3(TT / 128, CC / 128, BB), 256>>>(pwo, bo, pO, out);
}

// round 17
// speedup vs baseline: 1.1409x; 1.0207x over previous
#include <cuda_runtime.h>
#include <cuda_fp16.h>
#include <math.h>
#include <stdint.h>

#define BB 4
#define CC 512
#define TT 1024
#define HH 8
#define KCC 64
#define BHT (BB*HH)

// fp16 staging
__device__ __half g_Qh[BB*HH*TT*KCC];
__device__ __half g_Kh[BB*HH*TT*KCC];
__device__ __half g_Vh[BB*HH*TT*KCC];
__device__ __half g_Oh[BB*HH*TT*KCC];
__device__ __half g_xh[BB*CC*TT];
__device__ __half g_wqh[CC*CC];
__device__ __half g_wkh[CC*CC];
__device__ __half g_wvh[CC*CC];
__device__ __half g_woh[CC*CC];

// ---------------------------------------------------------------------------
// helpers
// ---------------------------------------------------------------------------
__device__ __forceinline__ unsigned h2pack(float x, float y) {
    __half2 t = __floats2half2_rn(x, y);
    return *reinterpret_cast<unsigned*>(&t);
}
__device__ __forceinline__ void mma_f16(float c[4], unsigned a0, unsigned a1,
                                        unsigned a2, unsigned a3,
                                        unsigned b0, unsigned b1) {
    asm volatile(
        "mma.sync.aligned.m16n8k16.row.col.f32.f16.f16.f32 "
        "{%0,%1,%2,%3},{%4,%5,%6,%7},{%8,%9},{%0,%1,%2,%3};"
        : "+f"(c[0]), "+f"(c[1]), "+f"(c[2]), "+f"(c[3])
        : "r"(a0), "r"(a1), "r"(a2), "r"(a3), "r"(b0), "r"(b1));
}
__device__ __forceinline__ void ldmx4(unsigned &r0, unsigned &r1, unsigned &r2, unsigned &r3,
                                      unsigned addr) {
    asm volatile("ldmatrix.sync.aligned.m8n8.x4.shared.b16 {%0,%1,%2,%3},[%4];"
        : "=r"(r0), "=r"(r1), "=r"(r2), "=r"(r3) : "r"(addr));
}
__device__ __forceinline__ void ldmx4t(unsigned &r0, unsigned &r1, unsigned &r2, unsigned &r3,
                                       unsigned addr) {
    asm volatile("ldmatrix.sync.aligned.m8n8.x4.trans.shared.b16 {%0,%1,%2,%3},[%4];"
        : "=r"(r0), "=r"(r1), "=r"(r2), "=r"(r3) : "r"(addr));
}
__device__ __forceinline__ void cpa16(unsigned dst, const void* src) {
    asm volatile("cp.async.cg.shared.global [%0], [%1], 16;" :: "r"(dst), "l"(src));
}
__device__ __forceinline__ void cp_commit() {
    asm volatile("cp.async.commit_group;");
}
template<int N> __device__ __forceinline__ void cp_wait() {
    asm volatile("cp.async.wait_group %0;" :: "n"(N));
}

// ---------------------------------------------------------------------------
// fp32 -> fp16 convert
// ---------------------------------------------------------------------------
__global__ void cvt_kernel(const float* __restrict__ x,
                           const float* __restrict__ wq, const float* __restrict__ wk,
                           const float* __restrict__ wv, const float* __restrict__ wo,
                           __half* __restrict__ xh,
                           __half* __restrict__ wqh, __half* __restrict__ wkh,
                           __half* __restrict__ wvh, __half* __restrict__ woh)
{
    const int sel = blockIdx.y;
    const float* src; __half* dst; int n;
    if (sel == 0)      { src = x;  dst = xh;  n = BB * CC * TT; }
    else if (sel == 1) { src = wq; dst = wqh; n = CC * CC; }
    else if (sel == 2) { src = wk; dst = wkh; n = CC * CC; }
    else if (sel == 3) { src = wv; dst = wvh; n = CC * CC; }
    else               { src = wo; dst = woh; n = CC * CC; }
    int i = (blockIdx.x * 256 + threadIdx.x) * 8;
    if (i >= n) return;
    float4 a = *(const float4*)(src + i);
    float4 b = *(const float4*)(src + i + 4);
    __half2 h0 = __floats2half2_rn(a.x, a.y);
    __half2 h1 = __floats2half2_rn(a.z, a.w);
    __half2 h2 = __floats2half2_rn(b.x, b.y);
    __half2 h3 = __floats2half2_rn(b.z, b.w);
    *(uint4*)(dst + i) = make_uint4(*(unsigned*)&h0, *(unsigned*)&h1,
                                    *(unsigned*)&h2, *(unsigned*)&h3);
}

// ---------------------------------------------------------------------------
// Fused QKV projection: 128x128, BK=32 double-buffered cp.async (R16).
// ---------------------------------------------------------------------------
__global__ __launch_bounds__(256, 2)
void proj3_kernel(const __half* __restrict__ wq, const float* __restrict__ bq,
                  const __half* __restrict__ wk, const float* __restrict__ bk,
                  const __half* __restrict__ wv, const float* __restrict__ bv,
                  const __half* __restrict__ x,
                  __half* __restrict__ pQ, __half* __restrict__ pK, __half* __restrict__ pV)
{
    const int z   = blockIdx.z;
    const int b   = z & 3;
    const int sel = z >> 2;
    const __half* w   = (sel == 0) ? wq : (sel == 1) ? wk : wv;
    const float* bias = (sel == 0) ? bq : (sel == 1) ? bk : bv;
    __half*      dst  = (sel == 0) ? pQ : (sel == 1) ? pK : pV;

    const int o0 = blockIdx.y * 128;
    const int t0 = blockIdx.x * 128;
    __shared__ __half As[2][128 * 40];
    __shared__ __half Xs[2][32 * 136];
    const int tid  = threadIdx.x;
    const int warp = tid >> 5, lane = tid & 31;
    const int m0 = (warp >> 1) * 32;
    const int n0 = (warp & 1) * 64;
    const int lq = lane >> 2, lr = lane & 3;
    const __half* xb = x + (size_t)b * CC * TT;

    const unsigned AsB = (unsigned)__cvta_generic_to_shared(&As[0][0]);
    const unsigned XsB = (unsigned)__cvta_generic_to_shared(&Xs[0][0]);

    const int wr0 = tid >> 2,            wk0 = (tid & 3) * 8;
    const int wr1 = (tid + 256) >> 2,    wk1 = (tid & 3) * 8;
    const int xk0 = tid >> 4,            xt0 = (tid & 15) * 8;
    const int xk1 = (tid + 256) >> 4,    xt1 = (tid & 15) * 8;
    const unsigned wdst0 = (wr0 * 40 + wk0) * 2, wdst1 = (wr1 * 40 + wk1) * 2;
    const unsigned xdst0 = (xk0 * 136 + xt0) * 2, xdst1 = (xk1 * 136 + xt1) * 2;
    const __half* wsrc0 = w + (size_t)(o0 + wr0) * CC + wk0;
    const __half* wsrc1 = w + (size_t)(o0 + wr1) * CC + wk1;
    const __half* xsrc0 = xb + (size_t)xk0 * TT + t0 + xt0;
    const __half* xsrc1 = xb + (size_t)xk1 * TT + t0 + xt1;

    cpa16(AsB + wdst0, wsrc0);
    cpa16(AsB + wdst1, wsrc1);
    cpa16(XsB + xdst0, xsrc0);
    cpa16(XsB + xdst1, xsrc1);
    cp_commit();

    const unsigned a_part = ((lane & 15) * 40 + (lane >> 4) * 8) * 2;
    const int mm = lane >> 3, r8 = lane & 7;
    const unsigned b_part = ((((mm & 1) * 8 + r8) * 136) + (mm >> 1) * 8) * 2;

    float acc[2][8][4] = {};

    for (int k0 = 0; k0 < CC; k0 += 32) {
        const int cur = (k0 >> 5) & 1;
        const bool more = (k0 + 32) < CC;
        if (more) {
            const int nxt = cur ^ 1;
            const int kn = k0 + 32;
            cpa16(AsB + nxt * 10240 + wdst0, wsrc0 + kn);
            cpa16(AsB + nxt * 10240 + wdst1, wsrc1 + kn);
            cpa16(XsB + nxt * 8704 + xdst0, xsrc0 + (size_t)kn * TT);
            cpa16(XsB + nxt * 8704 + xdst1, xsrc1 + (size_t)kn * TT);
            cp_commit();
            cp_wait<1>();
        } else {
            cp_wait<0>();
        }
        __syncthreads();

        #pragma unroll
        for (int ks = 0; ks < 32; ks += 16) {
            unsigned a0[4], a1[4];
            ldmx4(a0[0], a0[1], a0[2], a0[3],
                  AsB + cur * 10240 + m0 * 80 + ks * 2 + a_part);
            ldmx4(a1[0], a1[1], a1[2], a1[3],
                  AsB + cur * 10240 + (m0 + 16) * 80 + ks * 2 + a_part);
            #pragma unroll
            for (int nt = 0; nt < 4; nt++) {
                unsigned h0, h1, h2, h3;
                ldmx4t(h0, h1, h2, h3,
                       XsB + cur * 8704 + ks * 272 + (n0 + nt * 16) * 2 + b_part);
                mma_f16(acc[0][2*nt],   a0[0], a0[1], a0[2], a0[3], h0, h1);
                mma_f16(acc[0][2*nt+1], a0[0], a0[1], a0[2], a0[3], h2, h3);
                mma_f16(acc[1][2*nt],   a1[0], a1[1], a1[2], a1[3], h0, h1);
                mma_f16(acc[1][2*nt+1], a1[0], a1[1], a1[2], a1[3], h2, h3);
            }
        }
        __syncthreads();
    }

    #pragma unroll
    for (int mi = 0; mi < 2; mi++) {
        #pragma unroll
        for (int half = 0; half < 2; half++) {
            int o = o0 + m0 + mi * 16 + half * 8 + lq;
            float bvv = bias[o];
            int h = o >> 6, kc = o & 63;
            __half* drow = dst + ((size_t)(b * HH + h) * TT) * KCC + kc;
            #pragma unroll
            for (int nj = 0; nj < 8; nj++) {
                int t = t0 + n0 + nj * 8 + 2 * lr;
                drow[(size_t)t * KCC]       = __float2half_rn(acc[mi][nj][half * 2 + 0] + bvv);
                drow[(size_t)(t + 1) * KCC] = __float2half_rn(acc[mi][nj][half * 2 + 1] + bvv);
            }
        }
    }
}

// ---------------------------------------------------------------------------
// MMA banded flash attention; softmax uses fused exp2 (no scale pass).
// ---------------------------------------------------------------------------
#define ATTN_SMEM 69120
#define SCL 0.18033688f   // 0.125 * log2(e)

__global__ __launch_bounds__(256, 2)
void attn_mma_kernel(const __half* __restrict__ Q, const __half* __restrict__ K,
                     const __half* __restrict__ V, const float* __restrict__ embk,
                     const float* __restrict__ embv, __half* __restrict__ Out)
{
    extern __shared__ char smem[];
    __half* Qraw = (__half*)(smem);
    float* pe    = (float*)(smem + 55296);
    float* qe    = (float*)(smem + 59904);
    float* ek    = (float*)(smem + 64512);
    float* ev    = (float*)(smem + 66816);

    const int bh = blockIdx.y;
    const int t0 = blockIdx.x * 128;
    const int tid = threadIdx.x;
    const int w = tid >> 5, lane = tid & 31;
    const int lq = lane >> 2, lr = lane & 3;
    const int R0 = w * 16 + lq;

    const unsigned SB = (unsigned)__cvta_generic_to_shared(smem);
    const unsigned QrawB = SB;
    const unsigned KbB[2] = {SB + 18432, SB + 27648};
    const unsigned VbB[2] = {SB + 36864, SB + 46080};

    const __half* Qg  = Q + ((size_t)bh * TT + t0) * KCC;
    const __half* Kbh = K + (size_t)bh * TT * KCC;
    const __half* Vbh = V + (size_t)bh * TT * KCC;

    #pragma unroll
    for (int i = 0; i < 4; i++) {
        int ii = tid + i * 256;
        int r = ii >> 3, c8 = (ii & 7) * 8;
        cpa16(QrawB + (r * 72 + c8) * 2, Qg + r * 64 + c8);
    }
    cp_commit();
    #pragma unroll
    for (int i = 0; i < 2; i++) {
        int ii = tid + i * 256;
        int s = ii >> 3, c8 = (ii & 7) * 8;
        cpa16(KbB[0] + (s * 72 + c8) * 2, Kbh + s * 64 + c8);
        cpa16(VbB[0] + (s * 72 + c8) * 2, Vbh + s * 64 + c8);
    }
    cp_commit();

    for (int lin = tid; lin < 576; lin += 256) { ek[lin] = embk[lin]; ev[lin] = embv[lin]; }
    for (int lin = tid; lin < 1152; lin += 256) pe[lin] = 0.f;

    cp_wait<1>();
    __syncthreads();

    for (int idx = tid; idx < 1152; idx += 256) {
        int r = idx / 9, d = idx - r * 9;
        const __half2* q2 = (const __half2*)(Qraw + r * 72);
        const float* ekd = ek + d * 64;
        float s = 0.f;
        #pragma unroll 8
        for (int c = 0; c < 32; c++) {
            float2 f = __half22float2(q2[c]);
            s += f.x * ekd[2 * c] + f.y * ekd[2 * c + 1];
        }
        qe[idx] = s;
    }

    const unsigned q_part = ((lane & 15) * 72 + (lane >> 4) * 8) * 2;
    unsigned qf[4][4];
    #pragma unroll
    for (int ks = 0; ks < 4; ks++)
        ldmx4(qf[ks][0], qf[ks][1], qf[ks][2], qf[ks][3],
              QrawB + (w * 16 * 72) * 2 + ks * 32 + q_part);

    const int mm = lane >> 3, r8 = lane & 7;
    const unsigned k_part = ((((mm >> 1) * 8 + r8) * 72) + (mm & 1) * 8) * 2;
    const unsigned v_part = ((((mm & 1) * 8 + r8) * 72) + (mm >> 1) * 8) * 2;

    float S[8][4];
    float O[8][4] = {};
    float mr[2] = {-1e30f, -1e30f};   // raw-score space
    float lr2[2] = {0.f, 0.f};
    const int jlo = (t0 - 4) < 0 ? 0 : (t0 - 4) >> 6;
    const int jhi = ((t0 + 131) >> 6) > 15 ? 15 : (t0 + 131) >> 6;

    for (int j = 0; j < 16; j++) {
        const int s0 = j * 64;

        if (j < 15) {
            const int nb = (j + 1) & 1;
            #pragma unroll
            for (int i = 0; i < 2; i++) {
                int ii = tid + i * 256;
                int s = ii >> 3, c8 = (ii & 7) * 8;
                cpa16(KbB[nb] + (s * 72 + c8) * 2, Kbh + (size_t)(s0 + 64 + s) * 64 + c8);
                cpa16(VbB[nb] + (s * 72 + c8) * 2, Vbh + (size_t)(s0 + 64 + s) * 64 + c8);
            }
            cp_commit();
            cp_wait<1>();
        } else {
            cp_wait<0>();
        }
        __syncthreads();

        const unsigned Kj = KbB[j & 1];
        const unsigned Vj = VbB[j & 1];

        #pragma unroll
        for (int nt = 0; nt < 8; nt++)
            #pragma unroll
            for (int sl = 0; sl < 4; sl++) S[nt][sl] = 0.f;

        #pragma unroll
        for (int ks = 0; ks < 4; ks++) {
            #pragma unroll
            for (int ntp = 0; ntp < 4; ntp++) {
                unsigned h0, h1, h2, h3;
                ldmx4(h0, h1, h2, h3, Kj + ntp * 2304 + ks * 32 + k_part);
                mma_f16(S[2*ntp],   qf[ks][0], qf[ks][1], qf[ks][2], qf[ks][3], h0, h1);
                mma_f16(S[2*ntp+1], qf[ks][0], qf[ks][1], qf[ks][2], qf[ks][3], h2, h3);
            }
        }

        const bool band = (j >= jlo) && (j <= jhi);
        if (band) {
            #pragma unroll
            for (int nt = 0; nt < 8; nt++)
                #pragma unroll
                for (int sl = 0; sl < 4; sl++) {
                    int rl = R0 + ((sl >> 1) << 3);
                    int d = (s0 + nt * 8 + 2 * lr + (sl & 1)) - (t0 + rl) + 4;
                    if (d >= 0 && d <= 8) S[nt][sl] += qe[rl * 9 + d];
                }
        }

        // ---- online softmax (raw S; fused scale into exp2) ----
        float alpha[2];
        #pragma unroll
        for (int h = 0; h < 2; h++) {
            float mx = -1e30f;
            #pragma unroll
            for (int nt = 0; nt < 8; nt++)
                mx = fmaxf(mx, fmaxf(S[nt][2*h], S[nt][2*h+1]));
            mx = fmaxf(mx, __shfl_xor_sync(0xffffffffu, mx, 1));
            mx = fmaxf(mx, __shfl_xor_sync(0xffffffffu, mx, 2));
            float mn = fmaxf(mr[h], mx);
            alpha[h] = exp2f((mr[h] - mn) * SCL);
            const float mscl = mn * SCL;
            float rs = 0.f;
            #pragma unroll
            for (int nt = 0; nt < 8; nt++) {
                float p0 = exp2f(fmaf(S[nt][2*h],   SCL, -mscl));
                float p1 = exp2f(fmaf(S[nt][2*h+1], SCL, -mscl));
                S[nt][2*h] = p0; S[nt][2*h+1] = p1;
                rs += p0 + p1;
            }
            rs += __shfl_xor_sync(0xffffffffu, rs, 1);
            rs += __shfl_xor_sync(0xffffffffu, rs, 2);
            lr2[h] = lr2[h] * alpha[h] + rs;
            mr[h] = mn;
            #pragma unroll
            for (int nt = 0; nt < 8; nt++) { O[nt][2*h] *= alpha[h]; O[nt][2*h+1] *= alpha[h]; }
        }

        if (lr == 0) {
            #pragma unroll
            for (int h = 0; h < 2; h++)
                if (alpha[h] != 1.0f) {
                    #pragma unroll
                    for (int d = 0; d < 9; d++) pe[(R0 + 8*h) * 9 + d] *= alpha[h];
                }
        }
        __syncwarp();
        if (band) {
            #pragma unroll
            for (int nt = 0; nt < 8; nt++)
                #pragma unroll
                for (int sl = 0; sl < 4; sl++) {
                    int rl = R0 + ((sl >> 1) << 3);
                    int d = (s0 + nt * 8 + 2 * lr + (sl & 1)) - (t0 + rl) + 4;
                    if (d >= 0 && d <= 8) pe[rl * 9 + d] += S[nt][sl];
                }
        }
        __syncwarp();

        #pragma unroll
        for (int kp = 0; kp < 4; kp++) {
            unsigned p0 = h2pack(S[2*kp][0],   S[2*kp][1]);
            unsigned p1 = h2pack(S[2*kp][2],   S[2*kp][3]);
            unsigned p2 = h2pack(S[2*kp+1][0], S[2*kp+1][1]);
            unsigned p3 = h2pack(S[2*kp+1][2], S[2*kp+1][3]);
            #pragma unroll
            for (int ntp = 0; ntp < 4; ntp++) {
                unsigned h0, h1, h2, h3;
                ldmx4t(h0, h1, h2, h3, Vj + kp * 2304 + ntp * 32 + v_part);
                mma_f16(O[2*ntp],   p0, p1, p2, p3, h0, h1);
                mma_f16(O[2*ntp+1], p0, p1, p2, p3, h2, h3);
            }
        }
        __syncthreads();
    }

    float pev0[9], pev1[9];
    #pragma unroll
    for (int d = 0; d < 9; d++) { pev0[d] = pe[R0 * 9 + d]; pev1[d] = pe[(R0 + 8) * 9 + d]; }
    const float il0 = 1.f / lr2[0], il1 = 1.f / lr2[1];
    __half* Og = Out + ((size_t)bh * TT + t0) * KCC;
    #pragma unroll
    for (int nt = 0; nt < 8; nt++) {
        int c = nt * 8 + 2 * lr;
        float e0 = 0.f, e1 = 0.f, f0 = 0.f, f1 = 0.f;
        #pragma unroll
        for (int d = 0; d < 9; d++) {
            float v0 = ev[d * 64 + c], v1 = ev[d * 64 + c + 1];
            e0 += pev0[d] * v0; e1 += pev0[d] * v1;
            f0 += pev1[d] * v0; f1 += pev1[d] * v1;
        }
        *(__half2*)(Og + (size_t)R0 * 64 + c) =
            __floats2half2_rn((O[nt][0] + e0) * il0, (O[nt][1] + e1) * il0);
        *(__half2*)(Og + (size_t)(R0 + 8) * 64 + c) =
            __floats2half2_rn((O[nt][2] + f0) * il1, (O[nt][3] + f1) * il1);
    }
}

// ---------------------------------------------------------------------------
// Output projection: 128x128, BK=32 double-buffered cp.async (R16).
// ---------------------------------------------------------------------------
__global__ __launch_bounds__(256, 2)
void oproj_kernel(const __half* __restrict__ w, const float* __restrict__ bias,
                  const __half* __restrict__ A, float* __restrict__ out)
{
    const int b  = blockIdx.z;
    const int o0 = blockIdx.y * 128;
    const int t0 = blockIdx.x * 128;
    __shared__ __half As[2][128 * 40];
    __shared__ __half Xs[2][128 * 40];
    const int tid  = threadIdx.x;
    const int warp = tid >> 5, lane = tid & 31;
    const int m0 = (warp >> 1) * 32;
    const int n0 = (warp & 1) * 64;
    const int lq = lane >> 2, lr = lane & 3;

    const unsigned AsB = (unsigned)__cvta_generic_to_shared(&As[0][0]);
    const unsigned XsB = (unsigned)__cvta_generic_to_shared(&Xs[0][0]);

    const int wr0 = tid >> 2,         wk0 = (tid & 3) * 8;
    const int wr1 = (tid + 256) >> 2;
    const int xt0 = tid >> 2,         xk0 = (tid & 3) * 8;
    const int xt1 = (tid + 256) >> 2;
    const unsigned wdst0 = (wr0 * 40 + wk0) * 2, wdst1 = (wr1 * 40 + wk0) * 2;
    const unsigned xdst0 = (xt0 * 40 + xk0) * 2, xdst1 = (xt1 * 40 + xk0) * 2;
    const __half* wsrc0 = w + (size_t)(o0 + wr0) * CC + wk0;
    const __half* wsrc1 = w + (size_t)(o0 + wr1) * CC + wk0;
    const __half* Ab = A + (size_t)(b * HH) * TT * KCC;

    cpa16(AsB + wdst0, wsrc0);
    cpa16(AsB + wdst1, wsrc1);
    cpa16(XsB + xdst0, Ab + (size_t)(t0 + xt0) * KCC + xk0);
    cpa16(XsB + xdst1, Ab + (size_t)(t0 + xt1) * KCC + xk0);
    cp_commit();

    const unsigned a_part = ((lane & 15) * 40 + (lane >> 4) * 8) * 2;

    float acc[2][8][4] = {};

    for (int k0 = 0; k0 < CC; k0 += 32) {
        const int cur = (k0 >> 5) & 1;
        const bool more = (k0 + 32) < CC;
        if (more) {
            const int kn = k0 + 32;
            const int h = kn >> 6, kc0 = kn & 63;
            const int nxt = cur ^ 1;
            cpa16(AsB + nxt * 10240 + wdst0, wsrc0 + kn);
            cpa16(AsB + nxt * 10240 + wdst1, wsrc1 + kn);
            cpa16(XsB + nxt * 10240 + xdst0,
                  Ab + ((size_t)h * TT + t0 + xt0) * KCC + kc0 + xk0);
            cpa16(XsB + nxt * 10240 + xdst1,
                  Ab + ((size_t)h * TT + t0 + xt1) * KCC + kc0 + xk0);
            cp_commit();
            cp_wait<1>();
        } else {
            cp_wait<0>();
        }
        __syncthreads();

        #pragma unroll
        for (int ks = 0; ks < 32; ks += 16) {
            unsigned a0[4], a1[4];
            ldmx4(a0[0], a0[1], a0[2], a0[3],
                  AsB + cur * 10240 + m0 * 80 + ks * 2 + a_part);
            ldmx4(a1[0], a1[1], a1[2], a1[3],
                  AsB + cur * 10240 + (m0 + 16) * 80 + ks * 2 + a_part);
            #pragma unroll
            for (int nt = 0; nt < 4; nt++) {
                unsigned h0, h1, h2, h3;
                ldmx4(h0, h1, h2, h3,
                      XsB + cur * 10240 + (n0 + nt * 16) * 80 + ks * 2 + a_part);
                mma_f16(acc[0][2*nt],   a0[0], a0[1], a0[2], a0[3], h0, h2);
                mma_f16(acc[0][2*nt+1], a0[0], a0[1], a0[2], a0[3], h1, h3);
                mma_f16(acc[1][2*nt],   a1[0], a1[1], a1[2], a1[3], h0, h2);
                mma_f16(acc[1][2*nt+1], a1[0], a1[1], a1[2], a1[3], h1, h3);
            }
        }
        __syncthreads();
    }

    #pragma unroll
    for (int mi = 0; mi < 2; mi++) {
        #pragma unroll
        for (int half = 0; half < 2; half++) {
            int o = o0 + m0 + mi * 16 + half * 8 + lq;
            float bvv = bias[o];
            float* orow = out + ((size_t)b * CC + o) * TT;
            #pragma unroll
            for (int nj = 0; nj < 8; nj++) {
                int t = t0 + n0 + nj * 8 + 2 * lr;
                *(float2*)(orow + t) = make_float2(acc[mi][nj][half * 2 + 0] + bvv,
                                                   acc[mi][nj][half * 2 + 1] + bvv);
            }
        }
    }
}

// ---------------------------------------------------------------------------
extern "C" void kernel_launch(void* const* d_in, const int* in_sizes, int n_in,
                              void* d_out, int out_size)
{
    const float* x   = (const float*)d_in[0];
    const float* wq  = (const float*)d_in[1];
    const float* bq  = (const float*)d_in[2];
    const float* wk  = (const float*)d_in[3];
    const float* bk  = (const float*)d_in[4];
    const float* wv  = (const float*)d_in[5];
    const float* bv  = (const float*)d_in[6];
    const float* wo  = (const float*)d_in[7];
    const float* bo  = (const float*)d_in[8];
    const float* ek  = (const float*)d_in[9];
    const float* ev  = (const float*)d_in[10];
    float* out = (float*)d_out;

    __half *pQ, *pK, *pV, *pO, *pxh, *pwq, *pwk, *pwv, *pwo;
    cudaGetSymbolAddress((void**)&pQ,  g_Qh);
    cudaGetSymbolAddress((void**)&pK,  g_Kh);
    cudaGetSymbolAddress((void**)&pV,  g_Vh);
    cudaGetSymbolAddress((void**)&pO,  g_Oh);
    cudaGetSymbolAddress((void**)&pxh, g_xh);
    cudaGetSymbolAddress((void**)&pwq, g_wqh);
    cudaGetSymbolAddress((void**)&pwk, g_wkh);
    cudaGetSymbolAddress((void**)&pwv, g_wvh);
    cudaGetSymbolAddress((void**)&pwo, g_woh);

    static int configured = 0;
    if (!configured) {
        cudaFuncSetAttribute((const void*)attn_mma_kernel,
                             cudaFuncAttributeMaxDynamicSharedMemorySize, ATTN_SMEM);
        configured = 1;
    }

    cvt_kernel<<<dim3((BB * CC * TT) / 2048, 5), 256>>>(x, wq, wk, wv, wo,
                                                        pxh, pwq, pwk, pwv, pwo);
    proj3_kernel<<<dim3(TT / 128, CC / 128, BB * 3), 256>>>(pwq, bq, pwk, bk, pwv, bv,
                                                            pxh, pQ, pK, pV);
    attn_mma_kernel<<<dim3(TT / 128, BHT), 256, ATTN_SMEM>>>(pQ, pK, pV, ek, ev, pO);
    oproj_kernel<<<dim3(TT / 128, CC / 128, BB), 256>>>(pwo, bo, pO, out);
}